// round 3
// baseline (speedup 1.0000x reference)
#include <cuda_runtime.h>
#include <cstdint>

typedef unsigned long long u64;

__device__ __forceinline__ float ex2f(float x) {
    float y;
    asm("ex2.approx.ftz.f32 %0, %1;" : "=f"(y) : "f"(x));
    return y;
}
__device__ __forceinline__ u64 pk2(float lo, float hi) {
    u64 r; asm("mov.b64 %0, {%1, %2};" : "=l"(r) : "f"(lo), "f"(hi)); return r;
}
__device__ __forceinline__ void upk2(float& lo, float& hi, u64 v) {
    asm("mov.b64 {%0, %1}, %2;" : "=f"(lo), "=f"(hi) : "l"(v));
}
__device__ __forceinline__ u64 pk2i(unsigned lo, unsigned hi) {
    u64 r; asm("mov.b64 %0, {%1, %2};" : "=l"(r) : "r"(lo), "r"(hi)); return r;
}
__device__ __forceinline__ void upk2i(unsigned& lo, unsigned& hi, u64 v) {
    asm("mov.b64 {%0, %1}, %2;" : "=r"(lo), "=r"(hi) : "l"(v));
}
__device__ __forceinline__ u64 f2fma(u64 a, u64 b, u64 c) {
    u64 r; asm("fma.rn.f32x2 %0, %1, %2, %3;" : "=l"(r) : "l"(a), "l"(b), "l"(c)); return r;
}
__device__ __forceinline__ u64 f2add(u64 a, u64 b) {
    u64 r; asm("add.rn.f32x2 %0, %1, %2;" : "=l"(r) : "l"(a), "l"(b)); return r;
}

struct PolyC {
    u64 MP, NMP, N1P, C3, C2, C1, C0;
};

// One q on one k-pair via MUFU ex2 (2 scalar ex2; packed arg + packed accum)
__device__ __forceinline__ void slot_mufu(u64 tp, u64 nmp, u64 xkp, u64& se, u64& sa) {
    const u64 zp = f2fma(tp, xkp, nmp);
    float z0, z1;
    upk2(z0, z1, zp);
    const u64 ep = pk2(ex2f(z0), ex2f(z1));
    se = f2add(se, ep);
    sa = f2fma(xkp, ep, sa);
}

// One q on one k-pair via FMA-pipe packed exp2 (deg-3 minimax, ALU exponent inject)
__device__ __forceinline__ void slot_poly(u64 tp, u64 nmp, u64 xkp, u64& se, u64& sa,
                                          const PolyC& c) {
    const u64 zp = f2fma(tp, xkp, nmp);
    float z0, z1;
    upk2(z0, z1, zp);
    z0 = fmaxf(z0, -80.0f);   // guard exponent-injection wrap (ALU FMNMX)
    z1 = fmaxf(z1, -80.0f);
    const u64 zc = pk2(z0, z1);
    const u64 tpk = f2add(zc, c.MP);        // round-to-int in mantissa
    const u64 hpk = f2add(tpk, c.NMP);      // h = round(z)
    const u64 fpk = f2fma(hpk, c.N1P, zc);  // f = z - h, |f| <= 0.5
    u64 ppk = f2fma(c.C3, fpk, c.C2);
    ppk = f2fma(ppk, fpk, c.C1);
    ppk = f2fma(ppk, fpk, c.C0);
    unsigned tl, th, pl, ph;
    upk2i(tl, th, tpk);
    upk2i(pl, ph, ppk);
    const u64 ep = pk2i(pl + (tl << 23), ph + (th << 23));  // 2^n scale (ALU LEA)
    se = f2add(se, ep);
    sa = f2fma(xkp, ep, sa);
}

// Fused: warp 0 folds weights to 4 scalars; 1 warp = 1 batch row, 8 rows/block.
// Per 4-k group: 5 MUFU slots + 3 poly slots (f_eff = 1.5 -> balanced pipes).
__global__ __launch_bounds__(256) void attn_fused_kernel(
    const float* __restrict__ x, float* __restrict__ out, int B,
    const float* __restrict__ Wt, const float* __restrict__ bt,
    const float* __restrict__ Wq, const float* __restrict__ bq,
    const float* __restrict__ Wk, const float* __restrict__ bk,
    const float* __restrict__ Wv, const float* __restrict__ bv,
    const float* __restrict__ Wo, const float* __restrict__ bo) {
    __shared__ float sx[8][128];
    __shared__ float sc[4];

    const int warp = threadIdx.x >> 5;
    const int lane = threadIdx.x & 31;
    const int b = blockIdx.x * 8 + warp;
    const bool active = (b < B);

    float4 xv = make_float4(0.f, 0.f, 0.f, 0.f);
    if (active) {
        xv = reinterpret_cast<const float4*>(x + (size_t)b * 128)[lane];
        reinterpret_cast<float4*>(sx[warp])[lane] = xv;
    }

    if (warp == 0) {
        const int e = lane;
        float qv = 0.f, kv = 0.f, vv = 0.f, qb = 0.f, vb = 0.f;
#pragma unroll
        for (int d = 0; d < 32; d++) {
            const float wt  = Wt[d];
            const float btd = bt[d];
            qv = fmaf(wt,  Wq[d * 32 + e], qv);
            kv = fmaf(wt,  Wk[d * 32 + e], kv);
            vv = fmaf(wt,  Wv[d * 32 + e], vv);
            qb = fmaf(btd, Wq[d * 32 + e], qb);
            vb = fmaf(btd, Wv[d * 32 + e], vb);
        }
        qb += bq[e];
        vb += bv[e];
        const float wo = Wo[e];
        float a  = qv * kv;
        float c1 = qb * kv;
        float al = vv * wo;
        float be = vb * wo;
#pragma unroll
        for (int off = 16; off > 0; off >>= 1) {
            a  += __shfl_xor_sync(0xffffffffu, a,  off);
            c1 += __shfl_xor_sync(0xffffffffu, c1, off);
            al += __shfl_xor_sync(0xffffffffu, al, off);
            be += __shfl_xor_sync(0xffffffffu, be, off);
        }
        if (e == 0) {
            const float LOG2E = 1.4426950408889634f;
            const float INV_SQRT_D = 0.17677669529663687f;
            sc[0] = a  * INV_SQRT_D * LOG2E;
            sc[1] = c1 * INV_SQRT_D * LOG2E;
            sc[2] = al * (1.0f / 128.0f);
            sc[3] = be + bo[0];
        }
    }
    __syncthreads();
    if (!active) return;

    const float ta = sc[0];
    const float tc = sc[1];

    float mx = fmaxf(fmaxf(xv.x, xv.y), fmaxf(xv.z, xv.w));
    float mn = fminf(fminf(xv.x, xv.y), fminf(xv.z, xv.w));
#pragma unroll
    for (int off = 16; off > 0; off >>= 1) {
        mx = fmaxf(mx, __shfl_xor_sync(0xffffffffu, mx, off));
        mn = fminf(mn, __shfl_xor_sync(0xffffffffu, mn, off));
    }
    __syncwarp();

    const float t0 = fmaf(ta, xv.x, tc);
    const float t1 = fmaf(ta, xv.y, tc);
    const float t2 = fmaf(ta, xv.z, tc);
    const float t3 = fmaf(ta, xv.w, tc);
    const float nm0 = -((t0 > 0.f) ? t0 * mx : t0 * mn);
    const float nm1 = -((t1 > 0.f) ? t1 * mx : t1 * mn);
    const float nm2 = -((t2 > 0.f) ? t2 * mx : t2 * mn);
    const float nm3 = -((t3 > 0.f) ? t3 * mx : t3 * mn);

    const u64 t0p = pk2(t0, t0), nm0p = pk2(nm0, nm0);
    const u64 t1p = pk2(t1, t1), nm1p = pk2(nm1, nm1);
    const u64 t2p = pk2(t2, t2), nm2p = pk2(nm2, nm2);
    const u64 t3p = pk2(t3, t3), nm3p = pk2(nm3, nm3);

    PolyC pc;
    {
        const float MAGIC = 12582912.0f;  // 1.5 * 2^23
        pc.MP  = pk2(MAGIC, MAGIC);
        pc.NMP = pk2(-MAGIC, -MAGIC);
        pc.N1P = pk2(-1.0f, -1.0f);
        // deg-3 minimax for 2^f on [-0.5, 0.5] (Taylor + Remez absorption), rel err <= 1.2e-4
        pc.C3  = pk2(0.05583618f, 0.05583618f);
        pc.C2  = pk2(0.24262903f, 0.24262903f);
        pc.C1  = pk2(0.69314459f, 0.69314459f);
        pc.C0  = pk2(0.99992490f, 0.99992490f);
    }

    u64 se0 = 0ull, se1 = 0ull, se2 = 0ull, se3 = 0ull;
    u64 sa0 = 0ull, sa1 = 0ull, sa2 = 0ull, sa3 = 0ull;

    const float* s = sx[warp];

#pragma unroll 4
    for (int g = 0; g < 32; g++) {
        const float4 xg = reinterpret_cast<const float4*>(s)[g];  // LDS.128 broadcast
        const u64 xp0 = pk2(xg.x, xg.y);
        const u64 xp1 = pk2(xg.z, xg.w);

        // 5 MUFU slots
        slot_mufu(t0p, nm0p, xp0, se0, sa0);
        slot_mufu(t0p, nm0p, xp1, se0, sa0);
        slot_mufu(t1p, nm1p, xp0, se1, sa1);
        slot_mufu(t1p, nm1p, xp1, se1, sa1);
        slot_mufu(t2p, nm2p, xp0, se2, sa2);
        // 3 poly slots
        slot_poly(t2p, nm2p, xp1, se2, sa2, pc);
        slot_poly(t3p, nm3p, xp0, se3, sa3, pc);
        slot_poly(t3p, nm3p, xp1, se3, sa3, pc);
    }

    float lo, hi;
    upk2(lo, hi, se0); const float S0 = lo + hi;
    upk2(lo, hi, sa0); const float A0 = lo + hi;
    upk2(lo, hi, se1); const float S1 = lo + hi;
    upk2(lo, hi, sa1); const float A1 = lo + hi;
    upk2(lo, hi, se2); const float S2 = lo + hi;
    upk2(lo, hi, sa2); const float A2 = lo + hi;
    upk2(lo, hi, se3); const float S3 = lo + hi;
    upk2(lo, hi, sa3); const float A3 = lo + hi;

    float msum = __fdividef(A0, S0) + __fdividef(A1, S1)
               + __fdividef(A2, S2) + __fdividef(A3, S3);
#pragma unroll
    for (int off = 16; off > 0; off >>= 1)
        msum += __shfl_xor_sync(0xffffffffu, msum, off);

    if (lane == 0)
        out[b] = fmaf(sc[2], msum, sc[3]);
}

extern "C" void kernel_launch(void* const* d_in, const int* in_sizes, int n_in,
                              void* d_out, int out_size) {
    const float* x  = (const float*)d_in[0];
    const float* Wt = (const float*)d_in[1];
    const float* bt = (const float*)d_in[2];
    const float* Wq = (const float*)d_in[3];
    const float* bq = (const float*)d_in[4];
    const float* Wk = (const float*)d_in[5];
    const float* bk = (const float*)d_in[6];
    const float* Wv = (const float*)d_in[7];
    const float* bv = (const float*)d_in[8];
    const float* Wo = (const float*)d_in[9];
    const float* bo = (const float*)d_in[10];
    float* out = (float*)d_out;

    const int B = in_sizes[0] / 128;

    attn_fused_kernel<<<(B + 7) / 8, 256>>>(x, out, B,
                                            Wt, bt, Wq, bq, Wk, bk, Wv, bv, Wo, bo);
}

// round 4
// speedup vs baseline: 1.0688x; 1.0688x over previous
#include <cuda_runtime.h>

__device__ __forceinline__ float ex2f(float x) {
    float y;
    asm("ex2.approx.ftz.f32 %0, %1;" : "=f"(y) : "f"(x));
    return y;
}

// Per warp = one batch row.
//  1) m(t) = sum_k x_k 2^{t x_k} / sum_k 2^{t x_k} evaluated EXACTLY at 32
//     Chebyshev nodes spanning [t_lo, t_hi] (lane j owns node j).
//  2) DCT-32 (via shfl) -> Chebyshev coefficients.
//  3) Clenshaw evaluation of the interpolant at the 128 query points t_q.
// Exps per row: 32*128 = 4096 instead of 128*128 = 16384.
__global__ __launch_bounds__(256) void attn_cheb_kernel(
    const float* __restrict__ x, float* __restrict__ out, int B,
    const float* __restrict__ Wt, const float* __restrict__ bt,
    const float* __restrict__ Wq, const float* __restrict__ bq,
    const float* __restrict__ Wk, const float* __restrict__ bk,
    const float* __restrict__ Wv, const float* __restrict__ bv,
    const float* __restrict__ Wo, const float* __restrict__ bo) {
    __shared__ float sx[8][128];
    __shared__ float At[1024];  // At[j*32 + i] = DCT weight: coeff i, node j (conflict-free)
    __shared__ float cn[32];    // Chebyshev node positions cos(theta_j)
    __shared__ float sc[4];     // collapsed weights {ta, tc, alpha/128, beta}

    const int tid = threadIdx.x;
    const int warp = tid >> 5;
    const int lane = tid & 31;
    const int b = blockIdx.x * 8 + warp;
    const bool active = (b < B);

    // ---- one-time tables (per block; amortized) ----
    const float PI64 = 0.049087385212340517f;  // pi/64
    for (int idx = tid; idx < 1024; idx += 256) {
        const int i = idx >> 5, j = idx & 31;
        const float ang = (float)i * ((float)(2 * j + 1) * PI64);
        At[j * 32 + i] = cosf(ang) * (i == 0 ? (1.0f / 32.0f) : (2.0f / 32.0f));
    }
    if (tid < 32) cn[tid] = cosf((float)(2 * tid + 1) * PI64);

    float4 xv = make_float4(0.f, 0.f, 0.f, 0.f);
    if (active) {
        xv = reinterpret_cast<const float4*>(x + (size_t)b * 128)[lane];
        reinterpret_cast<float4*>(sx[warp])[lane] = xv;
    }

    // ---- weight collapse (warp 0; L2-served) ----
    if (warp == 0) {
        const int e = lane;
        float qv = 0.f, kv = 0.f, vv = 0.f, qb = 0.f, vb = 0.f;
#pragma unroll
        for (int d = 0; d < 32; d++) {
            const float wt  = Wt[d];
            const float btd = bt[d];
            qv = fmaf(wt,  Wq[d * 32 + e], qv);
            kv = fmaf(wt,  Wk[d * 32 + e], kv);
            vv = fmaf(wt,  Wv[d * 32 + e], vv);
            qb = fmaf(btd, Wq[d * 32 + e], qb);
            vb = fmaf(btd, Wv[d * 32 + e], vb);
        }
        qb += bq[e];
        vb += bv[e];
        const float wo = Wo[e];
        float a  = qv * kv;
        float c1 = qb * kv;
        float al = vv * wo;
        float be = vb * wo;
#pragma unroll
        for (int off = 16; off > 0; off >>= 1) {
            a  += __shfl_xor_sync(0xffffffffu, a,  off);
            c1 += __shfl_xor_sync(0xffffffffu, c1, off);
            al += __shfl_xor_sync(0xffffffffu, al, off);
            be += __shfl_xor_sync(0xffffffffu, be, off);
        }
        if (e == 0) {
            const float LOG2E = 1.4426950408889634f;
            const float INV_SQRT_D = 0.17677669529663687f;
            sc[0] = a  * INV_SQRT_D * LOG2E;
            sc[1] = c1 * INV_SQRT_D * LOG2E;
            sc[2] = al * (1.0f / 128.0f);
            sc[3] = be + bo[0];
        }
    }
    __syncthreads();
    if (!active) return;

    const float ta = sc[0];
    const float tc = sc[1];

    // row max / min
    float mx = fmaxf(fmaxf(xv.x, xv.y), fmaxf(xv.z, xv.w));
    float mn = fminf(fminf(xv.x, xv.y), fminf(xv.z, xv.w));
#pragma unroll
    for (int off = 16; off > 0; off >>= 1) {
        mx = fmaxf(mx, __shfl_xor_sync(0xffffffffu, mx, off));
        mn = fminf(mn, __shfl_xor_sync(0xffffffffu, mn, off));
    }
    __syncwarp();

    // t range covering all 128 queries
    const float tA = fmaf(ta, mn, tc);
    const float tB = fmaf(ta, mx, tc);
    const float tlo = fminf(tA, tB);
    const float thi = fmaxf(tA, tB);
    const float ctr = 0.5f * (tlo + thi);
    const float rad = fmaxf(0.5f * (thi - tlo), 1e-5f);
    const float invr = __fdividef(1.0f, rad);

    // ---- exact evaluation at this lane's Chebyshev node ----
    const float tj = fmaf(rad, cn[lane], ctr);
    const float stab = -((tj > 0.f) ? tj * mx : tj * mn);  // max_k tj*x_k
    float se = 0.f, sa = 0.f;
    const float* s = sx[warp];
#pragma unroll 8
    for (int k = 0; k < 128; k += 4) {
        const float4 xg = *reinterpret_cast<const float4*>(s + k);
        {
            const float e = ex2f(fmaf(tj, xg.x, stab));
            se += e; sa = fmaf(xg.x, e, sa);
        }
        {
            const float e = ex2f(fmaf(tj, xg.y, stab));
            se += e; sa = fmaf(xg.y, e, sa);
        }
        {
            const float e = ex2f(fmaf(tj, xg.z, stab));
            se += e; sa = fmaf(xg.z, e, sa);
        }
        {
            const float e = ex2f(fmaf(tj, xg.w, stab));
            se += e; sa = fmaf(xg.w, e, sa);
        }
    }
    const float mj = __fdividef(sa, se);  // m at node j (bounded in [mn, mx])

    // ---- DCT-32: lane i accumulates Chebyshev coefficient c_i ----
    float ci = 0.f;
#pragma unroll
    for (int j = 0; j < 32; j++) {
        const float mjj = __shfl_sync(0xffffffffu, mj, j);
        ci = fmaf(At[j * 32 + lane], mjj, ci);
    }

    // ---- Clenshaw at this lane's 4 query points ----
    const float s0 = fminf(1.f, fmaxf(-1.f, (fmaf(ta, xv.x, tc) - ctr) * invr));
    const float s1 = fminf(1.f, fmaxf(-1.f, (fmaf(ta, xv.y, tc) - ctr) * invr));
    const float s2 = fminf(1.f, fmaxf(-1.f, (fmaf(ta, xv.z, tc) - ctr) * invr));
    const float s3 = fminf(1.f, fmaxf(-1.f, (fmaf(ta, xv.w, tc) - ctr) * invr));
    const float d0 = 2.f * s0, d1 = 2.f * s1, d2 = 2.f * s2, d3 = 2.f * s3;

    float a1_0 = 0.f, a2_0 = 0.f;
    float a1_1 = 0.f, a2_1 = 0.f;
    float a1_2 = 0.f, a2_2 = 0.f;
    float a1_3 = 0.f, a2_3 = 0.f;
#pragma unroll
    for (int i = 31; i >= 1; i--) {
        const float civ = __shfl_sync(0xffffffffu, ci, i);
        float nb;
        nb = fmaf(d0, a1_0, civ - a2_0); a2_0 = a1_0; a1_0 = nb;
        nb = fmaf(d1, a1_1, civ - a2_1); a2_1 = a1_1; a1_1 = nb;
        nb = fmaf(d2, a1_2, civ - a2_2); a2_2 = a1_2; a1_2 = nb;
        nb = fmaf(d3, a1_3, civ - a2_3); a2_3 = a1_3; a1_3 = nb;
    }
    const float c0v = __shfl_sync(0xffffffffu, ci, 0);
    const float m0 = fmaf(s0, a1_0, c0v - a2_0);
    const float m1 = fmaf(s1, a1_1, c0v - a2_1);
    const float m2 = fmaf(s2, a1_2, c0v - a2_2);
    const float m3 = fmaf(s3, a1_3, c0v - a2_3);

    float msum = (m0 + m1) + (m2 + m3);
#pragma unroll
    for (int off = 16; off > 0; off >>= 1)
        msum += __shfl_xor_sync(0xffffffffu, msum, off);

    if (lane == 0)
        out[b] = fmaf(sc[2], msum, sc[3]);
}

extern "C" void kernel_launch(void* const* d_in, const int* in_sizes, int n_in,
                              void* d_out, int out_size) {
    const float* x  = (const float*)d_in[0];
    const float* Wt = (const float*)d_in[1];
    const float* bt = (const float*)d_in[2];
    const float* Wq = (const float*)d_in[3];
    const float* bq = (const float*)d_in[4];
    const float* Wk = (const float*)d_in[5];
    const float* bk = (const float*)d_in[6];
    const float* Wv = (const float*)d_in[7];
    const float* bv = (const float*)d_in[8];
    const float* Wo = (const float*)d_in[9];
    const float* bo = (const float*)d_in[10];
    float* out = (float*)d_out;

    const int B = in_sizes[0] / 128;

    attn_cheb_kernel<<<(B + 7) / 8, 256>>>(x, out, B,
                                           Wt, bt, Wq, bq, Wk, bk, Wv, bv, Wo, bo);
}

// round 5
// speedup vs baseline: 2.0637x; 1.9308x over previous
#include <cuda_runtime.h>

typedef unsigned long long u64;

__device__ __forceinline__ float ex2f(float x) {
    float y;
    asm("ex2.approx.ftz.f32 %0, %1;" : "=f"(y) : "f"(x));
    return y;
}
__device__ __forceinline__ float cosf_hw(float x) {
    float y;
    asm("cos.approx.ftz.f32 %0, %1;" : "=f"(y) : "f"(x));
    return y;
}
__device__ __forceinline__ u64 pk2(float lo, float hi) {
    u64 r; asm("mov.b64 %0, {%1, %2};" : "=l"(r) : "f"(lo), "f"(hi)); return r;
}
__device__ __forceinline__ void upk2(float& lo, float& hi, u64 v) {
    asm("mov.b64 {%0, %1}, %2;" : "=f"(lo), "=f"(hi) : "l"(v));
}
__device__ __forceinline__ u64 f2fma(u64 a, u64 b, u64 c) {
    u64 r; asm("fma.rn.f32x2 %0, %1, %2, %3;" : "=l"(r) : "l"(a), "l"(b), "l"(c)); return r;
}
__device__ __forceinline__ u64 f2add(u64 a, u64 b) {
    u64 r; asm("add.rn.f32x2 %0, %1, %2;" : "=l"(r) : "l"(a), "l"(b)); return r;
}

// Per warp = one batch row.
//  1) m(t) = sum_k x_k 2^{t x_k} / sum_k 2^{t x_k} evaluated exactly at 32
//     Chebyshev nodes spanning [t_lo, t_hi] (lane j owns node j).
//  2) DCT-32 (shfl) -> Chebyshev coefficients.
//  3) Packed Clenshaw at the 128 query points.
// DCT table built with integer mod-128 angle reduction + MUFU cos (cheap,
// conflict-free stores). Node loop and Clenshaw use fma.rn.f32x2.
__global__ __launch_bounds__(256) void attn_cheb_kernel(
    const float* __restrict__ x, float* __restrict__ out, int B,
    const float* __restrict__ Wt, const float* __restrict__ bt,
    const float* __restrict__ Wq, const float* __restrict__ bq,
    const float* __restrict__ Wk, const float* __restrict__ bk,
    const float* __restrict__ Wv, const float* __restrict__ bv,
    const float* __restrict__ Wo, const float* __restrict__ bo) {
    __shared__ float sx[8][128];
    __shared__ float At[1024];  // At[j*32 + i]: weight of node j in coeff i
    __shared__ float sc[4];     // {ta, tc, alpha/128, beta}

    const int tid = threadIdx.x;
    const int warp = tid >> 5;
    const int lane = tid & 31;
    const int b = blockIdx.x * 8 + warp;
    const bool active = (b < B);

    const float PI64 = 0.049087385212340517f;  // pi/64

    // ---- DCT table: At[j*32+i] = cos(i*(2j+1)*pi/64) * (i==0 ? 1/32 : 2/32)
    // consecutive idx -> consecutive smem (conflict-free); angle reduced mod 2*pi
    // via integer &127 so MUFU cos stays accurate.
#pragma unroll
    for (int idx = tid; idx < 1024; idx += 256) {
        const int j = idx >> 5, i = idx & 31;
        const int K = (i * (2 * j + 1)) & 127;
        At[idx] = cosf_hw((float)K * PI64) * (i == 0 ? (1.0f / 32.0f) : (2.0f / 32.0f));
    }

    float4 xv = make_float4(0.f, 0.f, 0.f, 0.f);
    if (active) {
        xv = reinterpret_cast<const float4*>(x + (size_t)b * 128)[lane];
        reinterpret_cast<float4*>(sx[warp])[lane] = xv;
    }

    // ---- weight collapse (warp 0; L2-served) ----
    if (warp == 0) {
        const int e = lane;
        float qv = 0.f, kv = 0.f, vv = 0.f, qb = 0.f, vb = 0.f;
#pragma unroll
        for (int d = 0; d < 32; d++) {
            const float wt  = Wt[d];
            const float btd = bt[d];
            qv = fmaf(wt,  Wq[d * 32 + e], qv);
            kv = fmaf(wt,  Wk[d * 32 + e], kv);
            vv = fmaf(wt,  Wv[d * 32 + e], vv);
            qb = fmaf(btd, Wq[d * 32 + e], qb);
            vb = fmaf(btd, Wv[d * 32 + e], vb);
        }
        qb += bq[e];
        vb += bv[e];
        const float wo = Wo[e];
        float a  = qv * kv;
        float c1 = qb * kv;
        float al = vv * wo;
        float be = vb * wo;
#pragma unroll
        for (int off = 16; off > 0; off >>= 1) {
            a  += __shfl_xor_sync(0xffffffffu, a,  off);
            c1 += __shfl_xor_sync(0xffffffffu, c1, off);
            al += __shfl_xor_sync(0xffffffffu, al, off);
            be += __shfl_xor_sync(0xffffffffu, be, off);
        }
        if (e == 0) {
            const float LOG2E = 1.4426950408889634f;
            const float INV_SQRT_D = 0.17677669529663687f;
            sc[0] = a  * INV_SQRT_D * LOG2E;
            sc[1] = c1 * INV_SQRT_D * LOG2E;
            sc[2] = al * (1.0f / 128.0f);
            sc[3] = be + bo[0];
        }
    }
    __syncthreads();
    if (!active) return;

    const float ta = sc[0];
    const float tc = sc[1];

    // row max / min
    float mx = fmaxf(fmaxf(xv.x, xv.y), fmaxf(xv.z, xv.w));
    float mn = fminf(fminf(xv.x, xv.y), fminf(xv.z, xv.w));
#pragma unroll
    for (int off = 16; off > 0; off >>= 1) {
        mx = fmaxf(mx, __shfl_xor_sync(0xffffffffu, mx, off));
        mn = fminf(mn, __shfl_xor_sync(0xffffffffu, mn, off));
    }
    __syncwarp();

    // t range covering all 128 queries
    const float tA = fmaf(ta, mn, tc);
    const float tB = fmaf(ta, mx, tc);
    const float tlo = fminf(tA, tB);
    const float thi = fmaxf(tA, tB);
    const float ctr = 0.5f * (tlo + thi);
    const float rad = fmaxf(0.5f * (thi - tlo), 1e-5f);
    const float invr = __fdividef(1.0f, rad);

    // this lane's Chebyshev node
    const float cnl = cosf_hw((float)(2 * lane + 1) * PI64);
    const float tj = fmaf(rad, cnl, ctr);
    const float stab = -((tj > 0.f) ? tj * mx : tj * mn);  // max_k tj*x_k

    // ---- exact node evaluation (packed f32x2) ----
    const u64 tjp = pk2(tj, tj);
    const u64 stp = pk2(stab, stab);
    u64 se2 = 0ull, sa2 = 0ull;
    const float* s = sx[warp];
#pragma unroll 8
    for (int k = 0; k < 128; k += 4) {
        const float4 xg = *reinterpret_cast<const float4*>(s + k);
        {
            const u64 xp = pk2(xg.x, xg.y);
            const u64 zp = f2fma(tjp, xp, stp);
            float z0, z1;
            upk2(z0, z1, zp);
            const u64 ep = pk2(ex2f(z0), ex2f(z1));
            se2 = f2add(se2, ep);
            sa2 = f2fma(xp, ep, sa2);
        }
        {
            const u64 xp = pk2(xg.z, xg.w);
            const u64 zp = f2fma(tjp, xp, stp);
            float z0, z1;
            upk2(z0, z1, zp);
            const u64 ep = pk2(ex2f(z0), ex2f(z1));
            se2 = f2add(se2, ep);
            sa2 = f2fma(xp, ep, sa2);
        }
    }
    float lo, hi;
    upk2(lo, hi, se2); const float se = lo + hi;
    upk2(lo, hi, sa2); const float sa = lo + hi;
    const float mj = __fdividef(sa, se);  // m at node j

    // ---- DCT-32: lane i accumulates Chebyshev coefficient c_i ----
    float ci = 0.f;
#pragma unroll
    for (int j = 0; j < 32; j++) {
        const float mjj = __shfl_sync(0xffffffffu, mj, j);
        ci = fmaf(At[j * 32 + lane], mjj, ci);
    }

    // ---- packed Clenshaw at this lane's 4 query points ----
    const float s0 = fminf(1.f, fmaxf(-1.f, (fmaf(ta, xv.x, tc) - ctr) * invr));
    const float s1 = fminf(1.f, fmaxf(-1.f, (fmaf(ta, xv.y, tc) - ctr) * invr));
    const float s2 = fminf(1.f, fmaxf(-1.f, (fmaf(ta, xv.z, tc) - ctr) * invr));
    const float s3 = fminf(1.f, fmaxf(-1.f, (fmaf(ta, xv.w, tc) - ctr) * invr));

    const u64 s01 = pk2(s0, s1), s23 = pk2(s2, s3);
    const u64 d01 = f2add(s01, s01), d23 = f2add(s23, s23);
    const u64 N1P = pk2(-1.0f, -1.0f);

    u64 a1_01 = 0ull, a2_01 = 0ull, a1_23 = 0ull, a2_23 = 0ull;
#pragma unroll
    for (int i = 31; i >= 1; i--) {
        const float civ = __shfl_sync(0xffffffffu, ci, i);
        const u64 cp = pk2(civ, civ);
        const u64 t01 = f2fma(a2_01, N1P, cp);  // civ - a2
        const u64 t23 = f2fma(a2_23, N1P, cp);
        const u64 n01 = f2fma(d01, a1_01, t01);
        const u64 n23 = f2fma(d23, a1_23, t23);
        a2_01 = a1_01; a1_01 = n01;
        a2_23 = a1_23; a1_23 = n23;
    }
    const float c0v = __shfl_sync(0xffffffffu, ci, 0);
    const u64 c0p = pk2(c0v, c0v);
    const u64 m01 = f2fma(s01, a1_01, f2fma(a2_01, N1P, c0p));
    const u64 m23 = f2fma(s23, a1_23, f2fma(a2_23, N1P, c0p));

    float m0, m1, m2, m3;
    upk2(m0, m1, m01);
    upk2(m2, m3, m23);

    float msum = (m0 + m1) + (m2 + m3);
#pragma unroll
    for (int off = 16; off > 0; off >>= 1)
        msum += __shfl_xor_sync(0xffffffffu, msum, off);

    if (lane == 0)
        out[b] = fmaf(sc[2], msum, sc[3]);
}

extern "C" void kernel_launch(void* const* d_in, const int* in_sizes, int n_in,
                              void* d_out, int out_size) {
    const float* x  = (const float*)d_in[0];
    const float* Wt = (const float*)d_in[1];
    const float* bt = (const float*)d_in[2];
    const float* Wq = (const float*)d_in[3];
    const float* bq = (const float*)d_in[4];
    const float* Wk = (const float*)d_in[5];
    const float* bk = (const float*)d_in[6];
    const float* Wv = (const float*)d_in[7];
    const float* bv = (const float*)d_in[8];
    const float* Wo = (const float*)d_in[9];
    const float* bo = (const float*)d_in[10];
    float* out = (float*)d_out;

    const int B = in_sizes[0] / 128;

    attn_cheb_kernel<<<(B + 7) / 8, 256>>>(x, out, B,
                                           Wt, bt, Wq, bq, Wk, bk, Wv, bv, Wo, bo);
}

// round 6
// speedup vs baseline: 2.2014x; 1.0667x over previous
#include <cuda_runtime.h>

typedef unsigned long long u64;

__device__ __forceinline__ float ex2f(float x) {
    float y;
    asm("ex2.approx.ftz.f32 %0, %1;" : "=f"(y) : "f"(x));
    return y;
}
__device__ __forceinline__ float cosf_hw(float x) {
    float y;
    asm("cos.approx.ftz.f32 %0, %1;" : "=f"(y) : "f"(x));
    return y;
}
__device__ __forceinline__ u64 pk2(float lo, float hi) {
    u64 r; asm("mov.b64 %0, {%1, %2};" : "=l"(r) : "f"(lo), "f"(hi)); return r;
}
__device__ __forceinline__ void upk2(float& lo, float& hi, u64 v) {
    asm("mov.b64 {%0, %1}, %2;" : "=f"(lo), "=f"(hi) : "l"(v));
}
__device__ __forceinline__ u64 f2fma(u64 a, u64 b, u64 c) {
    u64 r; asm("fma.rn.f32x2 %0, %1, %2, %3;" : "=l"(r) : "l"(a), "l"(b), "l"(c)); return r;
}
__device__ __forceinline__ u64 f2add(u64 a, u64 b) {
    u64 r; asm("add.rn.f32x2 %0, %1, %2;" : "=l"(r) : "l"(a), "l"(b)); return r;
}

// Per warp = one batch row. Split-interval Chebyshev:
//   [tlo,thi] split at ctr into halves A/B (radius rh = rad/2 each).
//   Lane h*16+i evaluates m(t) exactly at node i of half h (16 nodes/half).
//   DCT-16 per half -> coeffs stored in per-warp smem (32 floats).
//   Clenshaw-15 per query, half chosen by LDS index (no divergent shfl).
__global__ __launch_bounds__(256) void attn_cheb2_kernel(
    const float* __restrict__ x, float* __restrict__ out, int B,
    const float* __restrict__ Wt, const float* __restrict__ bt,
    const float* __restrict__ Wq, const float* __restrict__ bq,
    const float* __restrict__ Wk, const float* __restrict__ bk,
    const float* __restrict__ Wv, const float* __restrict__ bv,
    const float* __restrict__ Wo, const float* __restrict__ bo) {
    __shared__ float sx[8][128];
    __shared__ float At[256];   // At[j*16 + i]: weight of node j in coeff i (n=16)
    __shared__ float cf[8][32]; // per-warp coeffs: [0:16) half A, [16:32) half B
    __shared__ float sc[4];     // {ta, tc, alpha/128, beta}

    const int tid = threadIdx.x;
    const int warp = tid >> 5;
    const int lane = tid & 31;
    const int b = blockIdx.x * 8 + warp;
    const bool active = (b < B);

    const float PI32 = 0.09817477042468103f;  // pi/32

    // DCT-16 table: At[j*16+i] = cos(i*(2j+1)*pi/32) * (i==0 ? 1/16 : 2/16)
    // angle reduced mod 2*pi via integer &63; conflict-free consecutive stores.
    if (tid < 256) {
        const int j = tid >> 4, i = tid & 15;
        const int K = (i * (2 * j + 1)) & 63;
        At[tid] = cosf_hw((float)K * PI32) * (i == 0 ? (1.0f / 16.0f) : (2.0f / 16.0f));
    }

    float4 xv = make_float4(0.f, 0.f, 0.f, 0.f);
    if (active) {
        xv = reinterpret_cast<const float4*>(x + (size_t)b * 128)[lane];
        reinterpret_cast<float4*>(sx[warp])[lane] = xv;
    }

    // ---- weight collapse (warp 0; L2-served) ----
    if (warp == 0) {
        const int e = lane;
        float qv = 0.f, kv = 0.f, vv = 0.f, qb = 0.f, vb = 0.f;
#pragma unroll
        for (int d = 0; d < 32; d++) {
            const float wt  = Wt[d];
            const float btd = bt[d];
            qv = fmaf(wt,  Wq[d * 32 + e], qv);
            kv = fmaf(wt,  Wk[d * 32 + e], kv);
            vv = fmaf(wt,  Wv[d * 32 + e], vv);
            qb = fmaf(btd, Wq[d * 32 + e], qb);
            vb = fmaf(btd, Wv[d * 32 + e], vb);
        }
        qb += bq[e];
        vb += bv[e];
        const float wo = Wo[e];
        float a  = qv * kv;
        float c1 = qb * kv;
        float al = vv * wo;
        float be = vb * wo;
#pragma unroll
        for (int off = 16; off > 0; off >>= 1) {
            a  += __shfl_xor_sync(0xffffffffu, a,  off);
            c1 += __shfl_xor_sync(0xffffffffu, c1, off);
            al += __shfl_xor_sync(0xffffffffu, al, off);
            be += __shfl_xor_sync(0xffffffffu, be, off);
        }
        if (e == 0) {
            const float LOG2E = 1.4426950408889634f;
            const float INV_SQRT_D = 0.17677669529663687f;
            sc[0] = a  * INV_SQRT_D * LOG2E;
            sc[1] = c1 * INV_SQRT_D * LOG2E;
            sc[2] = al * (1.0f / 128.0f);
            sc[3] = be + bo[0];
        }
    }
    __syncthreads();
    if (!active) return;

    const float ta = sc[0];
    const float tc = sc[1];

    // row max / min
    float mx = fmaxf(fmaxf(xv.x, xv.y), fmaxf(xv.z, xv.w));
    float mn = fminf(fminf(xv.x, xv.y), fminf(xv.z, xv.w));
#pragma unroll
    for (int off = 16; off > 0; off >>= 1) {
        mx = fmaxf(mx, __shfl_xor_sync(0xffffffffu, mx, off));
        mn = fminf(mn, __shfl_xor_sync(0xffffffffu, mn, off));
    }
    __syncwarp();

    // t range; split into two halves
    const float tA = fmaf(ta, mn, tc);
    const float tB = fmaf(ta, mx, tc);
    const float tlo = fminf(tA, tB);
    const float thi = fmaxf(tA, tB);
    const float ctr = 0.5f * (tlo + thi);
    const float rad = fmaxf(0.5f * (thi - tlo), 1e-5f);
    const float rh = 0.5f * rad;                 // half-interval radius
    const float invrh = __fdividef(1.0f, rh);

    // this lane's node: half h = lane>>4, index i = lane&15
    const int h = lane >> 4;
    const int ni = lane & 15;
    const float chalf = h ? (ctr + rh) : (ctr - rh);
    const float gam = cosf_hw((float)(2 * ni + 1) * PI32);
    const float tj = fmaf(rh, gam, chalf);
    const float stab = -((tj > 0.f) ? tj * mx : tj * mn);  // max_k tj*x_k

    // ---- exact node evaluation (packed f32x2) ----
    const u64 tjp = pk2(tj, tj);
    const u64 stp = pk2(stab, stab);
    u64 se2 = 0ull, sa2 = 0ull;
    const float* s = sx[warp];
#pragma unroll 8
    for (int k = 0; k < 128; k += 4) {
        const float4 xg = *reinterpret_cast<const float4*>(s + k);
        {
            const u64 xp = pk2(xg.x, xg.y);
            const u64 zp = f2fma(tjp, xp, stp);
            float z0, z1;
            upk2(z0, z1, zp);
            const u64 ep = pk2(ex2f(z0), ex2f(z1));
            se2 = f2add(se2, ep);
            sa2 = f2fma(xp, ep, sa2);
        }
        {
            const u64 xp = pk2(xg.z, xg.w);
            const u64 zp = f2fma(tjp, xp, stp);
            float z0, z1;
            upk2(z0, z1, zp);
            const u64 ep = pk2(ex2f(z0), ex2f(z1));
            se2 = f2add(se2, ep);
            sa2 = f2fma(xp, ep, sa2);
        }
    }
    float lo, hi;
    upk2(lo, hi, se2); const float se = lo + hi;
    upk2(lo, hi, sa2); const float sa = lo + hi;
    const float mj = __fdividef(sa, se);  // m at this lane's node

    // ---- DCT-16 per half: lane (h, i) accumulates coeff c_i^h ----
    // node j of half h lives in lane h*16 + j (static per-lane shfl src)
    float ci = 0.f;
#pragma unroll
    for (int j = 0; j < 16; j++) {
        const float mjj = __shfl_sync(0xffffffffu, mj, h * 16 + j);
        ci = fmaf(At[j * 16 + ni], mjj, ci);
    }
    float* cw = cf[warp];
    cw[lane] = ci;      // [0:16) = half A coeffs, [16:32) = half B coeffs
    __syncwarp();

    // ---- Clenshaw-15 at this lane's 4 query points (half via LDS index) ----
    const float tq0 = fmaf(ta, xv.x, tc);
    const float tq1 = fmaf(ta, xv.y, tc);
    const float tq2 = fmaf(ta, xv.z, tc);
    const float tq3 = fmaf(ta, xv.w, tc);
    const int b0 = (tq0 >= ctr) ? 16 : 0;
    const int b1 = (tq1 >= ctr) ? 16 : 0;
    const int b2 = (tq2 >= ctr) ? 16 : 0;
    const int b3 = (tq3 >= ctr) ? 16 : 0;
    const float s0 = fminf(1.f, fmaxf(-1.f, (tq0 - (b0 ? ctr + rh : ctr - rh)) * invrh));
    const float s1 = fminf(1.f, fmaxf(-1.f, (tq1 - (b1 ? ctr + rh : ctr - rh)) * invrh));
    const float s2 = fminf(1.f, fmaxf(-1.f, (tq2 - (b2 ? ctr + rh : ctr - rh)) * invrh));
    const float s3 = fminf(1.f, fmaxf(-1.f, (tq3 - (b3 ? ctr + rh : ctr - rh)) * invrh));
    const float d0 = 2.f * s0, d1 = 2.f * s1, d2 = 2.f * s2, d3 = 2.f * s3;

    float a1_0 = 0.f, a2_0 = 0.f;
    float a1_1 = 0.f, a2_1 = 0.f;
    float a1_2 = 0.f, a2_2 = 0.f;
    float a1_3 = 0.f, a2_3 = 0.f;
#pragma unroll
    for (int i = 15; i >= 1; i--) {
        const float c0 = cw[b0 + i];
        const float c1 = cw[b1 + i];
        const float c2 = cw[b2 + i];
        const float c3 = cw[b3 + i];
        float nb;
        nb = fmaf(d0, a1_0, c0 - a2_0); a2_0 = a1_0; a1_0 = nb;
        nb = fmaf(d1, a1_1, c1 - a2_1); a2_1 = a1_1; a1_1 = nb;
        nb = fmaf(d2, a1_2, c2 - a2_2); a2_2 = a1_2; a1_2 = nb;
        nb = fmaf(d3, a1_3, c3 - a2_3); a2_3 = a1_3; a1_3 = nb;
    }
    const float m0 = fmaf(s0, a1_0, cw[b0] - a2_0);
    const float m1 = fmaf(s1, a1_1, cw[b1] - a2_1);
    const float m2 = fmaf(s2, a1_2, cw[b2] - a2_2);
    const float m3 = fmaf(s3, a1_3, cw[b3] - a2_3);

    float msum = (m0 + m1) + (m2 + m3);
#pragma unroll
    for (int off = 16; off > 0; off >>= 1)
        msum += __shfl_xor_sync(0xffffffffu, msum, off);

    if (lane == 0)
        out[b] = fmaf(sc[2], msum, sc[3]);
}

extern "C" void kernel_launch(void* const* d_in, const int* in_sizes, int n_in,
                              void* d_out, int out_size) {
    const float* x  = (const float*)d_in[0];
    const float* Wt = (const float*)d_in[1];
    const float* bt = (const float*)d_in[2];
    const float* Wq = (const float*)d_in[3];
    const float* bq = (const float*)d_in[4];
    const float* Wk = (const float*)d_in[5];
    const float* bk = (const float*)d_in[6];
    const float* Wv = (const float*)d_in[7];
    const float* bv = (const float*)d_in[8];
    const float* Wo = (const float*)d_in[9];
    const float* bo = (const float*)d_in[10];
    float* out = (float*)d_out;

    const int B = in_sizes[0] / 128;

    attn_cheb2_kernel<<<(B + 7) / 8, 256>>>(x, out, B,
                                            Wt, bt, Wq, bq, Wk, bk, Wv, bv, Wo, bo);
}

// round 10
// speedup vs baseline: 2.2569x; 1.0252x over previous
#include <cuda_runtime.h>

typedef unsigned long long u64;

__device__ __forceinline__ float ex2f(float x) {
    float y;
    asm("ex2.approx.ftz.f32 %0, %1;" : "=f"(y) : "f"(x));
    return y;
}
__device__ __forceinline__ float cosf_hw(float x) {
    float y;
    asm("cos.approx.ftz.f32 %0, %1;" : "=f"(y) : "f"(x));
    return y;
}
__device__ __forceinline__ u64 pk2(float lo, float hi) {
    u64 r; asm("mov.b64 %0, {%1, %2};" : "=l"(r) : "f"(lo), "f"(hi)); return r;
}
__device__ __forceinline__ void upk2(float& lo, float& hi, u64 v) {
    asm("mov.b64 {%0, %1}, %2;" : "=f"(lo), "=f"(hi) : "l"(v));
}
__device__ __forceinline__ u64 f2fma(u64 a, u64 b, u64 c) {
    u64 r; asm("fma.rn.f32x2 %0, %1, %2, %3;" : "=l"(r) : "l"(a), "l"(b), "l"(c)); return r;
}
__device__ __forceinline__ u64 f2add(u64 a, u64 b) {
    u64 r; asm("add.rn.f32x2 %0, %1, %2;" : "=l"(r) : "l"(a), "l"(b)); return r;
}

// Per warp = one batch row. Quarter-interval Chebyshev:
//   [tlo,thi] split into 4 quarters (radius rq = rad/4 each).
//   Lane h*8+i evaluates m(t) exactly at node i of quarter h (8 nodes/qtr).
//   DCT-8 per quarter -> 32 coeffs in per-warp smem.
//   Clenshaw-7 per query, quarter chosen by float->int index.
__global__ __launch_bounds__(256, 8) void attn_cheb4_kernel(
    const float* __restrict__ x, float* __restrict__ out, int B,
    const float* __restrict__ Wt, const float* __restrict__ bt,
    const float* __restrict__ Wq, const float* __restrict__ bq,
    const float* __restrict__ Wk, const float* __restrict__ bk,
    const float* __restrict__ Wv, const float* __restrict__ bv,
    const float* __restrict__ Wo, const float* __restrict__ bo) {
    __shared__ float sx[8][128];
    __shared__ float At[64];    // At[j*8 + i]: weight of node j in coeff i (n=8)
    __shared__ float cf[8][32]; // per-warp coeffs: quarter q at [q*8, q*8+8)
    __shared__ float sc[4];     // {ta, tc, alpha/128, beta}

    const int tid = threadIdx.x;
    const int warp = tid >> 5;
    const int lane = tid & 31;
    const int b = blockIdx.x * 8 + warp;
    const bool active = (b < B);

    const float PI16 = 0.19634954084936207f;  // pi/16

    // DCT-8 table: At[j*8+i] = cos(i*(2j+1)*pi/16) * (i==0 ? 1/8 : 2/8)
    if (tid < 64) {
        const int j = tid >> 3, i = tid & 7;
        const int K = (i * (2 * j + 1)) & 31;   // mod 2*pi
        At[tid] = cosf_hw((float)K * PI16) * (i == 0 ? 0.125f : 0.25f);
    }

    float4 xv = make_float4(0.f, 0.f, 0.f, 0.f);
    if (active) {
        xv = reinterpret_cast<const float4*>(x + (size_t)b * 128)[lane];
        reinterpret_cast<float4*>(sx[warp])[lane] = xv;
    }

    // ---- weight collapse (warp 0; L2-served) ----
    if (warp == 0) {
        const int e = lane;
        float qv = 0.f, kv = 0.f, vv = 0.f, qb = 0.f, vb = 0.f;
#pragma unroll
        for (int d = 0; d < 32; d++) {
            const float wt  = Wt[d];
            const float btd = bt[d];
            qv = fmaf(wt,  Wq[d * 32 + e], qv);
            kv = fmaf(wt,  Wk[d * 32 + e], kv);
            vv = fmaf(wt,  Wv[d * 32 + e], vv);
            qb = fmaf(btd, Wq[d * 32 + e], qb);
            vb = fmaf(btd, Wv[d * 32 + e], vb);
        }
        qb += bq[e];
        vb += bv[e];
        const float wo = Wo[e];
        float a  = qv * kv;
        float c1 = qb * kv;
        float al = vv * wo;
        float be = vb * wo;
#pragma unroll
        for (int off = 16; off > 0; off >>= 1) {
            a  += __shfl_xor_sync(0xffffffffu, a,  off);
            c1 += __shfl_xor_sync(0xffffffffu, c1, off);
            al += __shfl_xor_sync(0xffffffffu, al, off);
            be += __shfl_xor_sync(0xffffffffu, be, off);
        }
        if (e == 0) {
            const float LOG2E = 1.4426950408889634f;
            const float INV_SQRT_D = 0.17677669529663687f;
            sc[0] = a  * INV_SQRT_D * LOG2E;
            sc[1] = c1 * INV_SQRT_D * LOG2E;
            sc[2] = al * (1.0f / 128.0f);
            sc[3] = be + bo[0];
        }
    }
    __syncthreads();
    if (!active) return;

    const float ta = sc[0];
    const float tc = sc[1];

    // row max / min
    float mx = fmaxf(fmaxf(xv.x, xv.y), fmaxf(xv.z, xv.w));
    float mn = fminf(fminf(xv.x, xv.y), fminf(xv.z, xv.w));
#pragma unroll
    for (int off = 16; off > 0; off >>= 1) {
        mx = fmaxf(mx, __shfl_xor_sync(0xffffffffu, mx, off));
        mn = fminf(mn, __shfl_xor_sync(0xffffffffu, mn, off));
    }
    __syncwarp();

    // t range; 4 quarters of width qw = rad/2, radius rq = rad/4
    const float tA = fmaf(ta, mn, tc);
    const float tB = fmaf(ta, mx, tc);
    const float tlo = fminf(tA, tB);
    const float thi = fmaxf(tA, tB);
    const float rad = fmaxf(0.5f * (thi - tlo), 1e-5f);
    const float qw = 0.5f * rad;
    const float rq = 0.25f * rad;
    const float invqw = __fdividef(1.0f, qw);
    const float invrq = 2.0f * invqw;

    // this lane's node: quarter h = lane>>3, node index ni = lane&7
    const int h = lane >> 3;
    const int ni = lane & 7;
    const float cq = fmaf((float)h + 0.5f, qw, tlo);       // quarter center
    const float gam = cosf_hw((float)(2 * ni + 1) * PI16);
    const float tj = fmaf(rq, gam, cq);
    const float stab = -((tj > 0.f) ? tj * mx : tj * mn);  // max_k tj*x_k

    // ---- exact node evaluation (packed f32x2) ----
    const u64 tjp = pk2(tj, tj);
    const u64 stp = pk2(stab, stab);
    u64 se2 = 0ull, sa2 = 0ull;
    const float* s = sx[warp];
#pragma unroll 8
    for (int k = 0; k < 128; k += 4) {
        const float4 xg = *reinterpret_cast<const float4*>(s + k);
        {
            const u64 xp = pk2(xg.x, xg.y);
            const u64 zp = f2fma(tjp, xp, stp);
            float z0, z1;
            upk2(z0, z1, zp);
            const u64 ep = pk2(ex2f(z0), ex2f(z1));
            se2 = f2add(se2, ep);
            sa2 = f2fma(xp, ep, sa2);
        }
        {
            const u64 xp = pk2(xg.z, xg.w);
            const u64 zp = f2fma(tjp, xp, stp);
            float z0, z1;
            upk2(z0, z1, zp);
            const u64 ep = pk2(ex2f(z0), ex2f(z1));
            se2 = f2add(se2, ep);
            sa2 = f2fma(xp, ep, sa2);
        }
    }
    float lo, hi;
    upk2(lo, hi, se2); const float se = lo + hi;
    upk2(lo, hi, sa2); const float sa = lo + hi;
    const float mj = __fdividef(sa, se);  // m at this lane's node

    // ---- DCT-8 per quarter: lane (h, ni) accumulates coeff ni of quarter h
    float ci = 0.f;
    const int hbase = lane & 24;  // h*8
#pragma unroll
    for (int j = 0; j < 8; j++) {
        const float mjj = __shfl_sync(0xffffffffu, mj, hbase + j);
        ci = fmaf(At[j * 8 + ni], mjj, ci);
    }
    float* cw = cf[warp];
    cw[lane] = ci;
    __syncwarp();

    // ---- Clenshaw-7 at this lane's 4 query points ----
    const float tq0 = fmaf(ta, xv.x, tc);
    const float tq1 = fmaf(ta, xv.y, tc);
    const float tq2 = fmaf(ta, xv.z, tc);
    const float tq3 = fmaf(ta, xv.w, tc);
    const int q0 = min(3, max(0, __float2int_rd((tq0 - tlo) * invqw)));
    const int q1 = min(3, max(0, __float2int_rd((tq1 - tlo) * invqw)));
    const int q2 = min(3, max(0, __float2int_rd((tq2 - tlo) * invqw)));
    const int q3 = min(3, max(0, __float2int_rd((tq3 - tlo) * invqw)));
    const int b0 = q0 << 3, b1 = q1 << 3, b2 = q2 << 3, b3 = q3 << 3;
    const float c0q = fmaf((float)q0 + 0.5f, qw, tlo);
    const float c1q = fmaf((float)q1 + 0.5f, qw, tlo);
    const float c2q = fmaf((float)q2 + 0.5f, qw, tlo);
    const float c3q = fmaf((float)q3 + 0.5f, qw, tlo);
    const float s0 = fminf(1.f, fmaxf(-1.f, (tq0 - c0q) * invrq));
    const float s1 = fminf(1.f, fmaxf(-1.f, (tq1 - c1q) * invrq));
    const float s2 = fminf(1.f, fmaxf(-1.f, (tq2 - c2q) * invrq));
    const float s3 = fminf(1.f, fmaxf(-1.f, (tq3 - c3q) * invrq));
    const float d0 = 2.f * s0, d1 = 2.f * s1, d2 = 2.f * s2, d3 = 2.f * s3;

    float a1_0 = 0.f, a2_0 = 0.f;
    float a1_1 = 0.f, a2_1 = 0.f;
    float a1_2 = 0.f, a2_2 = 0.f;
    float a1_3 = 0.f, a2_3 = 0.f;
#pragma unroll
    for (int i = 7; i >= 1; i--) {
        const float cc0 = cw[b0 + i];
        const float cc1 = cw[b1 + i];
        const float cc2 = cw[b2 + i];
        const float cc3 = cw[b3 + i];
        float nb;
        nb = fmaf(d0, a1_0, cc0 - a2_0); a2_0 = a1_0; a1_0 = nb;
        nb = fmaf(d1, a1_1, cc1 - a2_1); a2_1 = a1_1; a1_1 = nb;
        nb = fmaf(d2, a1_2, cc2 - a2_2); a2_2 = a1_2; a1_2 = nb;
        nb = fmaf(d3, a1_3, cc3 - a2_3); a2_3 = a1_3; a1_3 = nb;
    }
    const float m0 = fmaf(s0, a1_0, cw[b0] - a2_0);
    const float m1 = fmaf(s1, a1_1, cw[b1] - a2_1);
    const float m2 = fmaf(s2, a1_2, cw[b2] - a2_2);
    const float m3 = fmaf(s3, a1_3, cw[b3] - a2_3);

    float msum = (m0 + m1) + (m2 + m3);
#pragma unroll
    for (int off = 16; off > 0; off >>= 1)
        msum += __shfl_xor_sync(0xffffffffu, msum, off);

    if (lane == 0)
        out[b] = fmaf(sc[2], msum, sc[3]);
}

extern "C" void kernel_launch(void* const* d_in, const int* in_sizes, int n_in,
                              void* d_out, int out_size) {
    const float* x  = (const float*)d_in[0];
    const float* Wt = (const float*)d_in[1];
    const float* bt = (const float*)d_in[2];
    const float* Wq = (const float*)d_in[3];
    const float* bq = (const float*)d_in[4];
    const float* Wk = (const float*)d_in[5];
    const float* bk = (const float*)d_in[6];
    const float* Wv = (const float*)d_in[7];
    const float* bv = (const float*)d_in[8];
    const float* Wo = (const float*)d_in[9];
    const float* bo = (const float*)d_in[10];
    float* out = (float*)d_out;

    const int B = in_sizes[0] / 128;

    attn_cheb4_kernel<<<(B + 7) / 8, 256>>>(x, out, B,
                                            Wt, bt, Wq, bq, Wk, bk, Wv, bv, Wo, bo);
}

// round 11
// speedup vs baseline: 2.6111x; 1.1569x over previous
#include <cuda_runtime.h>

typedef unsigned long long u64;

__device__ __forceinline__ float ex2f(float x) {
    float y;
    asm("ex2.approx.ftz.f32 %0, %1;" : "=f"(y) : "f"(x));
    return y;
}
__device__ __forceinline__ float cosf_hw(float x) {
    float y;
    asm("cos.approx.ftz.f32 %0, %1;" : "=f"(y) : "f"(x));
    return y;
}
__device__ __forceinline__ u64 pk2(float lo, float hi) {
    u64 r; asm("mov.b64 %0, {%1, %2};" : "=l"(r) : "f"(lo), "f"(hi)); return r;
}
__device__ __forceinline__ void upk2(float& lo, float& hi, u64 v) {
    asm("mov.b64 {%0, %1}, %2;" : "=f"(lo), "=f"(hi) : "l"(v));
}
__device__ __forceinline__ u64 f2fma(u64 a, u64 b, u64 c) {
    u64 r; asm("fma.rn.f32x2 %0, %1, %2, %3;" : "=l"(r) : "l"(a), "l"(b), "l"(c)); return r;
}
__device__ __forceinline__ u64 f2add(u64 a, u64 b) {
    u64 r; asm("add.rn.f32x2 %0, %1, %2;" : "=l"(r) : "l"(a), "l"(b)); return r;
}

// Per warp = one batch row. Quarter-interval Chebyshev (8 nodes/quarter).
// Weight collapse parallelized: warps 0-5 each produce one 32-vector
// (qv,kv,vv,qb,vb,wo) with high-MLP coalesced LDGs; ONE barrier; then every
// warp redundantly folds the vectors into 4 scalars (packed butterfly).
// Clenshaw coefficients travel via dynamic-source shfl (no smem, no conflicts).
__global__ __launch_bounds__(256, 8) void attn_cheb4_kernel(
    const float* __restrict__ x, float* __restrict__ out, int B,
    const float* __restrict__ Wt, const float* __restrict__ bt,
    const float* __restrict__ Wq, const float* __restrict__ bq,
    const float* __restrict__ Wk, const float* __restrict__ bk,
    const float* __restrict__ Wv, const float* __restrict__ bv,
    const float* __restrict__ Wo, const float* __restrict__ bo) {
    __shared__ float sx[8][128];
    __shared__ float At[64];    // At[j*8 + i]: DCT-8 weight of node j in coeff i
    __shared__ float sv[6][32]; // collapsed vectors: qv,kv,vv,qb,vb,wo

    const int tid = threadIdx.x;
    const int warp = tid >> 5;
    const int lane = tid & 31;
    const int b = blockIdx.x * 8 + warp;
    const bool active = (b < B);

    const float PI16 = 0.19634954084936207f;  // pi/16

    const float bo0 = bo[0];  // broadcast LDG, issued early

    float4 xv = make_float4(0.f, 0.f, 0.f, 0.f);
    if (active) {
        xv = reinterpret_cast<const float4*>(x + (size_t)b * 128)[lane];
        reinterpret_cast<float4*>(sx[warp])[lane] = xv;
    }

    // ---- parallel weight collapse: one dot product per warp ----
    if (warp < 6) {
        const int e = lane;
        float acc;
        if (warp == 5) {
            acc = Wo[e];
        } else {
            const float* M = (warp == 0 || warp == 3) ? Wq : ((warp == 1) ? Wk : Wv);
            const float* v = (warp < 3) ? Wt : bt;
            acc = 0.f;
#pragma unroll 16
            for (int d = 0; d < 32; d++)
                acc = fmaf(v[d], M[d * 32 + e], acc);
            if (warp == 3) acc += bq[e];
            if (warp == 4) acc += bv[e];
        }
        sv[warp][e] = acc;
    }

    // ---- DCT-8 table (concurrent with collapse) ----
    if (tid >= 192) {
        const int u = tid - 192;   // 0..63 (warps 6,7 — idle in collapse)
        const int j = u >> 3, i = u & 7;
        const int K = (i * (2 * j + 1)) & 31;
        At[u] = cosf_hw((float)K * PI16) * (i == 0 ? 0.125f : 0.25f);
    }
    __syncthreads();
    if (!active) return;

    // ---- every warp folds the 6 vectors into 4 scalars (no 2nd barrier) ----
    float ta, tc, alpha, beta;
    {
        const int e = lane;
        const float qv = sv[0][e], kv = sv[1][e], vv = sv[2][e];
        const float qb = sv[3][e], vb = sv[4][e], wo = sv[5][e];
        u64 P = pk2(qv * kv, qb * kv);   // {a, c1} partials
        u64 Q = pk2(vv * wo, vb * wo);   // {al, be} partials
#pragma unroll
        for (int off = 16; off > 0; off >>= 1) {
            P = f2add(P, __shfl_xor_sync(0xffffffffu, P, off));
            Q = f2add(Q, __shfl_xor_sync(0xffffffffu, Q, off));
        }
        float a, c1, al, be;
        upk2(a, c1, P);
        upk2(al, be, Q);
        const float LOG2E = 1.4426950408889634f;
        const float INV_SQRT_D = 0.17677669529663687f;
        ta = a  * INV_SQRT_D * LOG2E;
        tc = c1 * INV_SQRT_D * LOG2E;
        alpha = al * (1.0f / 128.0f);
        beta = be + bo0;
    }

    // row max / min
    float mx = fmaxf(fmaxf(xv.x, xv.y), fmaxf(xv.z, xv.w));
    float mn = fminf(fminf(xv.x, xv.y), fminf(xv.z, xv.w));
#pragma unroll
    for (int off = 16; off > 0; off >>= 1) {
        mx = fmaxf(mx, __shfl_xor_sync(0xffffffffu, mx, off));
        mn = fminf(mn, __shfl_xor_sync(0xffffffffu, mn, off));
    }
    __syncwarp();

    // t range; 4 quarters of width qw = rad/2, radius rq = rad/4
    const float tA = fmaf(ta, mn, tc);
    const float tB = fmaf(ta, mx, tc);
    const float tlo = fminf(tA, tB);
    const float thi = fmaxf(tA, tB);
    const float rad = fmaxf(0.5f * (thi - tlo), 1e-5f);
    const float qw = 0.5f * rad;
    const float rq = 0.25f * rad;
    const float invqw = __fdividef(1.0f, qw);
    const float invrq = 2.0f * invqw;

    // this lane's node: quarter h = lane>>3, node index ni = lane&7
    const int ni = lane & 7;
    const float cq = fmaf((float)(lane >> 3) + 0.5f, qw, tlo);  // quarter center
    const float gam = cosf_hw((float)(2 * ni + 1) * PI16);
    const float tj = fmaf(rq, gam, cq);
    const float stab = -((tj > 0.f) ? tj * mx : tj * mn);  // max_k tj*x_k

    // ---- exact node evaluation (packed f32x2) ----
    const u64 tjp = pk2(tj, tj);
    const u64 stp = pk2(stab, stab);
    u64 se2 = 0ull, sa2 = 0ull;
    const float* s = sx[warp];
#pragma unroll 8
    for (int k = 0; k < 128; k += 4) {
        const float4 xg = *reinterpret_cast<const float4*>(s + k);
        {
            const u64 xp = pk2(xg.x, xg.y);
            const u64 zp = f2fma(tjp, xp, stp);
            float z0, z1;
            upk2(z0, z1, zp);
            const u64 ep = pk2(ex2f(z0), ex2f(z1));
            se2 = f2add(se2, ep);
            sa2 = f2fma(xp, ep, sa2);
        }
        {
            const u64 xp = pk2(xg.z, xg.w);
            const u64 zp = f2fma(tjp, xp, stp);
            float z0, z1;
            upk2(z0, z1, zp);
            const u64 ep = pk2(ex2f(z0), ex2f(z1));
            se2 = f2add(se2, ep);
            sa2 = f2fma(xp, ep, sa2);
        }
    }
    float lo, hi;
    upk2(lo, hi, se2); const float se = lo + hi;
    upk2(lo, hi, sa2); const float sa = lo + hi;
    const float mj = __fdividef(sa, se);  // m at this lane's node

    // ---- DCT-8 per quarter: lane (h, ni) accumulates coeff ni of quarter h
    float ci = 0.f;
    const int hbase = lane & 24;  // h*8
#pragma unroll
    for (int j = 0; j < 8; j++) {
        const float mjj = __shfl_sync(0xffffffffu, mj, hbase + j);
        ci = fmaf(At[j * 8 + ni], mjj, ci);
    }
    // coeff i of quarter q now lives in lane q*8 + i

    // ---- Clenshaw-7 at this lane's 4 query points (coeffs via dynamic shfl)
    const float tq0 = fmaf(ta, xv.x, tc);
    const float tq1 = fmaf(ta, xv.y, tc);
    const float tq2 = fmaf(ta, xv.z, tc);
    const float tq3 = fmaf(ta, xv.w, tc);
    const int q0 = min(3, max(0, __float2int_rd((tq0 - tlo) * invqw)));
    const int q1 = min(3, max(0, __float2int_rd((tq1 - tlo) * invqw)));
    const int q2 = min(3, max(0, __float2int_rd((tq2 - tlo) * invqw)));
    const int q3 = min(3, max(0, __float2int_rd((tq3 - tlo) * invqw)));
    const int b0 = q0 << 3, b1 = q1 << 3, b2 = q2 << 3, b3 = q3 << 3;
    const float c0q = fmaf((float)q0 + 0.5f, qw, tlo);
    const float c1q = fmaf((float)q1 + 0.5f, qw, tlo);
    const float c2q = fmaf((float)q2 + 0.5f, qw, tlo);
    const float c3q = fmaf((float)q3 + 0.5f, qw, tlo);
    const float s0 = fminf(1.f, fmaxf(-1.f, (tq0 - c0q) * invrq));
    const float s1 = fminf(1.f, fmaxf(-1.f, (tq1 - c1q) * invrq));
    const float s2 = fminf(1.f, fmaxf(-1.f, (tq2 - c2q) * invrq));
    const float s3 = fminf(1.f, fmaxf(-1.f, (tq3 - c3q) * invrq));
    const float d0 = 2.f * s0, d1 = 2.f * s1, d2 = 2.f * s2, d3 = 2.f * s3;

    float a1_0 = 0.f, a2_0 = 0.f;
    float a1_1 = 0.f, a2_1 = 0.f;
    float a1_2 = 0.f, a2_2 = 0.f;
    float a1_3 = 0.f, a2_3 = 0.f;
#pragma unroll
    for (int i = 7; i >= 1; i--) {
        const float cc0 = __shfl_sync(0xffffffffu, ci, b0 + i);
        const float cc1 = __shfl_sync(0xffffffffu, ci, b1 + i);
        const float cc2 = __shfl_sync(0xffffffffu, ci, b2 + i);
        const float cc3 = __shfl_sync(0xffffffffu, ci, b3 + i);
        float nb;
        nb = fmaf(d0, a1_0, cc0 - a2_0); a2_0 = a1_0; a1_0 = nb;
        nb = fmaf(d1, a1_1, cc1 - a2_1); a2_1 = a1_1; a1_1 = nb;
        nb = fmaf(d2, a1_2, cc2 - a2_2); a2_2 = a1_2; a1_2 = nb;
        nb = fmaf(d3, a1_3, cc3 - a2_3); a2_3 = a1_3; a1_3 = nb;
    }
    const float cz0 = __shfl_sync(0xffffffffu, ci, b0);
    const float cz1 = __shfl_sync(0xffffffffu, ci, b1);
    const float cz2 = __shfl_sync(0xffffffffu, ci, b2);
    const float cz3 = __shfl_sync(0xffffffffu, ci, b3);
    const float m0 = fmaf(s0, a1_0, cz0 - a2_0);
    const float m1 = fmaf(s1, a1_1, cz1 - a2_1);
    const float m2 = fmaf(s2, a1_2, cz2 - a2_2);
    const float m3 = fmaf(s3, a1_3, cz3 - a2_3);

    float msum = (m0 + m1) + (m2 + m3);
#pragma unroll
    for (int off = 16; off > 0; off >>= 1)
        msum += __shfl_xor_sync(0xffffffffu, msum, off);

    if (lane == 0)
        out[b] = fmaf(alpha, msum, beta);
}

extern "C" void kernel_launch(void* const* d_in, const int* in_sizes, int n_in,
                              void* d_out, int out_size) {
    const float* x  = (const float*)d_in[0];
    const float* Wt = (const float*)d_in[1];
    const float* bt = (const float*)d_in[2];
    const float* Wq = (const float*)d_in[3];
    const float* bq = (const float*)d_in[4];
    const float* Wk = (const float*)d_in[5];
    const float* bk = (const float*)d_in[6];
    const float* Wv = (const float*)d_in[7];
    const float* bv = (const float*)d_in[8];
    const float* Wo = (const float*)d_in[9];
    const float* bo = (const float*)d_in[10];
    float* out = (float*)d_out;

    const int B = in_sizes[0] / 128;
    (void)bk;  // cancels exactly in softmax

    attn_cheb4_kernel<<<(B + 7) / 8, 256>>>(x, out, B,
                                            Wt, bt, Wq, bq, Wk, bk, Wv, bv, Wo, bo);
}

// round 12
// speedup vs baseline: 2.6781x; 1.0256x over previous
#include <cuda_runtime.h>

typedef unsigned long long u64;

__device__ float4 g_c;  // {ta, tc, alpha/128, beta}

__device__ __forceinline__ float ex2f(float x) {
    float y;
    asm("ex2.approx.ftz.f32 %0, %1;" : "=f"(y) : "f"(x));
    return y;
}
__device__ __forceinline__ float cosf_hw(float x) {
    float y;
    asm("cos.approx.ftz.f32 %0, %1;" : "=f"(y) : "f"(x));
    return y;
}
__device__ __forceinline__ u64 pk2(float lo, float hi) {
    u64 r; asm("mov.b64 %0, {%1, %2};" : "=l"(r) : "f"(lo), "f"(hi)); return r;
}
__device__ __forceinline__ void upk2(float& lo, float& hi, u64 v) {
    asm("mov.b64 {%0, %1}, %2;" : "=f"(lo), "=f"(hi) : "l"(v));
}
__device__ __forceinline__ u64 f2fma(u64 a, u64 b, u64 c) {
    u64 r; asm("fma.rn.f32x2 %0, %1, %2, %3;" : "=l"(r) : "l"(a), "l"(b), "l"(c)); return r;
}
__device__ __forceinline__ u64 f2add(u64 a, u64 b) {
    u64 r; asm("add.rn.f32x2 %0, %1, %2;" : "=l"(r) : "l"(a), "l"(b)); return r;
}

// One block, 192 threads: warps 0-4 compute the five 32-length dot products,
// warp 5 loads Wo; fold + write the 4 collapsed scalars to g_c.
__global__ void precompute_kernel(const float* __restrict__ Wt, const float* __restrict__ bt,
                                  const float* __restrict__ Wq, const float* __restrict__ bq,
                                  const float* __restrict__ Wk, const float* __restrict__ bk,
                                  const float* __restrict__ Wv, const float* __restrict__ bv,
                                  const float* __restrict__ Wo, const float* __restrict__ bo) {
    __shared__ float sv[6][32];
    const int warp = threadIdx.x >> 5;
    const int lane = threadIdx.x & 31;

    if (warp < 6) {
        const int e = lane;
        float acc;
        if (warp == 5) {
            acc = Wo[e];
        } else {
            const float* M = (warp == 0 || warp == 3) ? Wq : ((warp == 1) ? Wk : Wv);
            const float* v = (warp < 3) ? Wt : bt;
            acc = 0.f;
#pragma unroll 16
            for (int d = 0; d < 32; d++)
                acc = fmaf(v[d], M[d * 32 + e], acc);
            if (warp == 3) acc += bq[e];
            if (warp == 4) acc += bv[e];
        }
        sv[warp][e] = acc;
    }
    __syncthreads();

    if (warp == 0) {
        const int e = lane;
        const float qv = sv[0][e], kv = sv[1][e], vv = sv[2][e];
        const float qb = sv[3][e], vb = sv[4][e], wo = sv[5][e];
        float a  = qv * kv;
        float c1 = qb * kv;
        float al = vv * wo;
        float be = vb * wo;
#pragma unroll
        for (int off = 16; off > 0; off >>= 1) {
            a  += __shfl_xor_sync(0xffffffffu, a,  off);
            c1 += __shfl_xor_sync(0xffffffffu, c1, off);
            al += __shfl_xor_sync(0xffffffffu, al, off);
            be += __shfl_xor_sync(0xffffffffu, be, off);
        }
        if (e == 0) {
            const float LOG2E = 1.4426950408889634f;
            const float INV_SQRT_D = 0.17677669529663687f;
            g_c = make_float4(a * INV_SQRT_D * LOG2E,
                              c1 * INV_SQRT_D * LOG2E,
                              al * (1.0f / 128.0f),
                              be + bo[0]);
        }
    }
}

// Per warp = one batch row. Quarter-interval Chebyshev (8 nodes/quarter):
// exact node eval (packed f32x2 + MUFU ex2), DCT-8 per quarter, Clenshaw-7
// with coefficients traveling via dynamic-source shfl. Collapsed weights
// arrive via one broadcast LDG.128 of g_c (precomputed).
__global__ __launch_bounds__(256, 8) void attn_cheb4_kernel(
    const float* __restrict__ x, float* __restrict__ out, int B) {
    __shared__ float sx[8][128];
    __shared__ float At[64];    // At[j*8 + i]: DCT-8 weight of node j in coeff i

    const int tid = threadIdx.x;
    const int warp = tid >> 5;
    const int lane = tid & 31;
    const int b = blockIdx.x * 8 + warp;
    const bool active = (b < B);

    const float PI16 = 0.19634954084936207f;  // pi/16

    const float4 c = g_c;  // broadcast LDG.128 (L2-hit), overlaps x load
    const float ta = c.x, tc = c.y, alpha = c.z, beta = c.w;

    float4 xv = make_float4(0.f, 0.f, 0.f, 0.f);
    if (active) {
        xv = reinterpret_cast<const float4*>(x + (size_t)b * 128)[lane];
        reinterpret_cast<float4*>(sx[warp])[lane] = xv;
    }

    // DCT-8 table (tiny; only barrier dependency)
    if (tid < 64) {
        const int j = tid >> 3, i = tid & 7;
        const int K = (i * (2 * j + 1)) & 31;
        At[tid] = cosf_hw((float)K * PI16) * (i == 0 ? 0.125f : 0.25f);
    }
    __syncthreads();
    if (!active) return;

    // row max / min
    float mx = fmaxf(fmaxf(xv.x, xv.y), fmaxf(xv.z, xv.w));
    float mn = fminf(fminf(xv.x, xv.y), fminf(xv.z, xv.w));
#pragma unroll
    for (int off = 16; off > 0; off >>= 1) {
        mx = fmaxf(mx, __shfl_xor_sync(0xffffffffu, mx, off));
        mn = fminf(mn, __shfl_xor_sync(0xffffffffu, mn, off));
    }
    __syncwarp();

    // t range; 4 quarters of width qw = rad/2, radius rq = rad/4
    const float tA = fmaf(ta, mn, tc);
    const float tB = fmaf(ta, mx, tc);
    const float tlo = fminf(tA, tB);
    const float thi = fmaxf(tA, tB);
    const float rad = fmaxf(0.5f * (thi - tlo), 1e-5f);
    const float qw = 0.5f * rad;
    const float rq = 0.25f * rad;
    const float invqw = __fdividef(1.0f, qw);
    const float invrq = 2.0f * invqw;

    // this lane's node: quarter h = lane>>3, node index ni = lane&7
    const int ni = lane & 7;
    const float cq = fmaf((float)(lane >> 3) + 0.5f, qw, tlo);  // quarter center
    const float gam = cosf_hw((float)(2 * ni + 1) * PI16);
    const float tj = fmaf(rq, gam, cq);
    const float stab = -((tj > 0.f) ? tj * mx : tj * mn);  // max_k tj*x_k

    // ---- exact node evaluation (packed f32x2) ----
    const u64 tjp = pk2(tj, tj);
    const u64 stp = pk2(stab, stab);
    u64 se2 = 0ull, sa2 = 0ull;
    const float* s = sx[warp];
#pragma unroll 8
    for (int k = 0; k < 128; k += 4) {
        const float4 xg = *reinterpret_cast<const float4*>(s + k);
        {
            const u64 xp = pk2(xg.x, xg.y);
            const u64 zp = f2fma(tjp, xp, stp);
            float z0, z1;
            upk2(z0, z1, zp);
            const u64 ep = pk2(ex2f(z0), ex2f(z1));
            se2 = f2add(se2, ep);
            sa2 = f2fma(xp, ep, sa2);
        }
        {
            const u64 xp = pk2(xg.z, xg.w);
            const u64 zp = f2fma(tjp, xp, stp);
            float z0, z1;
            upk2(z0, z1, zp);
            const u64 ep = pk2(ex2f(z0), ex2f(z1));
            se2 = f2add(se2, ep);
            sa2 = f2fma(xp, ep, sa2);
        }
    }
    float lo, hi;
    upk2(lo, hi, se2); const float se = lo + hi;
    upk2(lo, hi, sa2); const float sa = lo + hi;
    const float mj = __fdividef(sa, se);  // m at this lane's node

    // ---- DCT-8 per quarter: lane (h, ni) accumulates coeff ni of quarter h
    float ci = 0.f;
    const int hbase = lane & 24;  // h*8
#pragma unroll
    for (int j = 0; j < 8; j++) {
        const float mjj = __shfl_sync(0xffffffffu, mj, hbase + j);
        ci = fmaf(At[j * 8 + ni], mjj, ci);
    }
    // coeff i of quarter q now lives in lane q*8 + i

    // ---- Clenshaw-7 at this lane's 4 query points (coeffs via dynamic shfl)
    const float tq0 = fmaf(ta, xv.x, tc);
    const float tq1 = fmaf(ta, xv.y, tc);
    const float tq2 = fmaf(ta, xv.z, tc);
    const float tq3 = fmaf(ta, xv.w, tc);
    const int q0 = min(3, max(0, __float2int_rd((tq0 - tlo) * invqw)));
    const int q1 = min(3, max(0, __float2int_rd((tq1 - tlo) * invqw)));
    const int q2 = min(3, max(0, __float2int_rd((tq2 - tlo) * invqw)));
    const int q3 = min(3, max(0, __float2int_rd((tq3 - tlo) * invqw)));
    const int b0 = q0 << 3, b1 = q1 << 3, b2 = q2 << 3, b3 = q3 << 3;
    const float c0q = fmaf((float)q0 + 0.5f, qw, tlo);
    const float c1q = fmaf((float)q1 + 0.5f, qw, tlo);
    const float c2q = fmaf((float)q2 + 0.5f, qw, tlo);
    const float c3q = fmaf((float)q3 + 0.5f, qw, tlo);
    const float s0 = fminf(1.f, fmaxf(-1.f, (tq0 - c0q) * invrq));
    const float s1 = fminf(1.f, fmaxf(-1.f, (tq1 - c1q) * invrq));
    const float s2 = fminf(1.f, fmaxf(-1.f, (tq2 - c2q) * invrq));
    const float s3 = fminf(1.f, fmaxf(-1.f, (tq3 - c3q) * invrq));
    const float d0 = 2.f * s0, d1 = 2.f * s1, d2 = 2.f * s2, d3 = 2.f * s3;

    float a1_0 = 0.f, a2_0 = 0.f;
    float a1_1 = 0.f, a2_1 = 0.f;
    float a1_2 = 0.f, a2_2 = 0.f;
    float a1_3 = 0.f, a2_3 = 0.f;
#pragma unroll
    for (int i = 7; i >= 1; i--) {
        const float cc0 = __shfl_sync(0xffffffffu, ci, b0 + i);
        const float cc1 = __shfl_sync(0xffffffffu, ci, b1 + i);
        const float cc2 = __shfl_sync(0xffffffffu, ci, b2 + i);
        const float cc3 = __shfl_sync(0xffffffffu, ci, b3 + i);
        float nb;
        nb = fmaf(d0, a1_0, cc0 - a2_0); a2_0 = a1_0; a1_0 = nb;
        nb = fmaf(d1, a1_1, cc1 - a2_1); a2_1 = a1_1; a1_1 = nb;
        nb = fmaf(d2, a1_2, cc2 - a2_2); a2_2 = a1_2; a1_2 = nb;
        nb = fmaf(d3, a1_3, cc3 - a2_3); a2_3 = a1_3; a1_3 = nb;
    }
    const float cz0 = __shfl_sync(0xffffffffu, ci, b0);
    const float cz1 = __shfl_sync(0xffffffffu, ci, b1);
    const float cz2 = __shfl_sync(0xffffffffu, ci, b2);
    const float cz3 = __shfl_sync(0xffffffffu, ci, b3);
    const float m0 = fmaf(s0, a1_0, cz0 - a2_0);
    const float m1 = fmaf(s1, a1_1, cz1 - a2_1);
    const float m2 = fmaf(s2, a1_2, cz2 - a2_2);
    const float m3 = fmaf(s3, a1_3, cz3 - a2_3);

    float msum = (m0 + m1) + (m2 + m3);
#pragma unroll
    for (int off = 16; off > 0; off >>= 1)
        msum += __shfl_xor_sync(0xffffffffu, msum, off);

    if (lane == 0)
        out[b] = fmaf(alpha, msum, beta);
}

extern "C" void kernel_launch(void* const* d_in, const int* in_sizes, int n_in,
                              void* d_out, int out_size) {
    const float* x  = (const float*)d_in[0];
    const float* Wt = (const float*)d_in[1];
    const float* bt = (const float*)d_in[2];
    const float* Wq = (const float*)d_in[3];
    const float* bq = (const float*)d_in[4];
    const float* Wk = (const float*)d_in[5];
    const float* bk = (const float*)d_in[6];
    const float* Wv = (const float*)d_in[7];
    const float* bv = (const float*)d_in[8];
    const float* Wo = (const float*)d_in[9];
    const float* bo = (const float*)d_in[10];
    float* out = (float*)d_out;

    const int B = in_sizes[0] / 128;

    precompute_kernel<<<1, 192>>>(Wt, bt, Wq, bq, Wk, bk, Wv, bv, Wo, bo);
    attn_cheb4_kernel<<<(B + 7) / 8, 256>>>(x, out, B);
}

// round 13
// speedup vs baseline: 2.8313x; 1.0572x over previous
#include <cuda_runtime.h>

typedef unsigned long long u64;

__device__ float4 g_c;  // {ta, tc, alpha/128, beta}

__device__ __forceinline__ float ex2f(float x) {
    float y;
    asm("ex2.approx.ftz.f32 %0, %1;" : "=f"(y) : "f"(x));
    return y;
}
__device__ __forceinline__ float cosf_hw(float x) {
    float y;
    asm("cos.approx.ftz.f32 %0, %1;" : "=f"(y) : "f"(x));
    return y;
}
__device__ __forceinline__ u64 pk2(float lo, float hi) {
    u64 r; asm("mov.b64 %0, {%1, %2};" : "=l"(r) : "f"(lo), "f"(hi)); return r;
}
__device__ __forceinline__ void upk2(float& lo, float& hi, u64 v) {
    asm("mov.b64 {%0, %1}, %2;" : "=f"(lo), "=f"(hi) : "l"(v));
}
__device__ __forceinline__ u64 f2fma(u64 a, u64 b, u64 c) {
    u64 r; asm("fma.rn.f32x2 %0, %1, %2, %3;" : "=l"(r) : "l"(a), "l"(b), "l"(c)); return r;
}
__device__ __forceinline__ u64 f2add(u64 a, u64 b) {
    u64 r; asm("add.rn.f32x2 %0, %1, %2;" : "=l"(r) : "l"(a), "l"(b)); return r;
}

// One block, 192 threads: warps 0-4 compute the five 32-length dot products,
// warp 5 loads Wo; fold + write the 4 collapsed scalars to g_c.
__global__ void precompute_kernel(const float* __restrict__ Wt, const float* __restrict__ bt,
                                  const float* __restrict__ Wq, const float* __restrict__ bq,
                                  const float* __restrict__ Wk, const float* __restrict__ bk,
                                  const float* __restrict__ Wv, const float* __restrict__ bv,
                                  const float* __restrict__ Wo, const float* __restrict__ bo) {
    __shared__ float sv[6][32];
    const int warp = threadIdx.x >> 5;
    const int lane = threadIdx.x & 31;

    if (warp < 6) {
        const int e = lane;
        float acc;
        if (warp == 5) {
            acc = Wo[e];
        } else {
            const float* M = (warp == 0 || warp == 3) ? Wq : ((warp == 1) ? Wk : Wv);
            const float* v = (warp < 3) ? Wt : bt;
            acc = 0.f;
#pragma unroll 16
            for (int d = 0; d < 32; d++)
                acc = fmaf(v[d], M[d * 32 + e], acc);
            if (warp == 3) acc += bq[e];
            if (warp == 4) acc += bv[e];
        }
        sv[warp][e] = acc;
    }
    __syncthreads();

    if (warp == 0) {
        const int e = lane;
        const float qv = sv[0][e], kv = sv[1][e], vv = sv[2][e];
        const float qb = sv[3][e], vb = sv[4][e], wo = sv[5][e];
        float a  = qv * kv;
        float c1 = qb * kv;
        float al = vv * wo;
        float be = vb * wo;
#pragma unroll
        for (int off = 16; off > 0; off >>= 1) {
            a  += __shfl_xor_sync(0xffffffffu, a,  off);
            c1 += __shfl_xor_sync(0xffffffffu, c1, off);
            al += __shfl_xor_sync(0xffffffffu, al, off);
            be += __shfl_xor_sync(0xffffffffu, be, off);
        }
        if (e == 0) {
            const float LOG2E = 1.4426950408889634f;
            const float INV_SQRT_D = 0.17677669529663687f;
            g_c = make_float4(a * INV_SQRT_D * LOG2E,
                              c1 * INV_SQRT_D * LOG2E,
                              al * (1.0f / 128.0f),
                              be + bo[0]);
        }
    }
}

// Per warp = one batch row. Quarter-interval Chebyshev (8 nodes/quarter).
// PDL secondary: everything not needing g_c runs before
// cudaGridDependencySynchronize(), overlapping the precompute kernel.
__global__ __launch_bounds__(256, 8) void attn_cheb4_kernel(
    const float* __restrict__ x, float* __restrict__ out, int B) {
    __shared__ float sx[8][128];
    __shared__ float At[64];    // At[j*8 + i]: DCT-8 weight of node j in coeff i

    const int tid = threadIdx.x;
    const int warp = tid >> 5;
    const int lane = tid & 31;
    const int b = blockIdx.x * 8 + warp;
    const bool active = (b < B);

    const float PI16 = 0.19634954084936207f;  // pi/16

    float4 xv = make_float4(0.f, 0.f, 0.f, 0.f);
    if (active) {
        xv = reinterpret_cast<const float4*>(x + (size_t)b * 128)[lane];
        reinterpret_cast<float4*>(sx[warp])[lane] = xv;
    }

    // DCT-8 table (independent of g_c)
    if (tid < 64) {
        const int j = tid >> 3, i = tid & 7;
        const int K = (i * (2 * j + 1)) & 31;
        At[tid] = cosf_hw((float)K * PI16) * (i == 0 ? 0.125f : 0.25f);
    }
    __syncthreads();
    if (!active) return;

    // row max / min (independent of g_c)
    float mx = fmaxf(fmaxf(xv.x, xv.y), fmaxf(xv.z, xv.w));
    float mn = fminf(fminf(xv.x, xv.y), fminf(xv.z, xv.w));
#pragma unroll
    for (int off = 16; off > 0; off >>= 1) {
        mx = fmaxf(mx, __shfl_xor_sync(0xffffffffu, mx, off));
        mn = fminf(mn, __shfl_xor_sync(0xffffffffu, mn, off));
    }
    __syncwarp();

    // Wait for the precompute grid, then read collapsed weights.
    cudaGridDependencySynchronize();
    const float4 c = g_c;  // broadcast LDG.128
    const float ta = c.x, tc = c.y, alpha = c.z, beta = c.w;

    // t range; 4 quarters of width qw = rad/2, radius rq = rad/4
    const float tA = fmaf(ta, mn, tc);
    const float tB = fmaf(ta, mx, tc);
    const float tlo = fminf(tA, tB);
    const float thi = fmaxf(tA, tB);
    const float rad = fmaxf(0.5f * (thi - tlo), 1e-5f);
    const float qw = 0.5f * rad;
    const float rq = 0.25f * rad;
    const float invqw = __fdividef(1.0f, qw);
    const float invrq = 2.0f * invqw;

    // this lane's node: quarter h = lane>>3, node index ni = lane&7
    const int ni = lane & 7;
    const float cq = fmaf((float)(lane >> 3) + 0.5f, qw, tlo);  // quarter center
    const float gam = cosf_hw((float)(2 * ni + 1) * PI16);
    const float tj = fmaf(rq, gam, cq);
    const float stab = -((tj > 0.f) ? tj * mx : tj * mn);  // max_k tj*x_k

    // ---- exact node evaluation (packed f32x2) ----
    const u64 tjp = pk2(tj, tj);
    const u64 stp = pk2(stab, stab);
    u64 se2 = 0ull, sa2 = 0ull;
    const float* s = sx[warp];
#pragma unroll 8
    for (int k = 0; k < 128; k += 4) {
        const float4 xg = *reinterpret_cast<const float4*>(s + k);
        {
            const u64 xp = pk2(xg.x, xg.y);
            const u64 zp = f2fma(tjp, xp, stp);
            float z0, z1;
            upk2(z0, z1, zp);
            const u64 ep = pk2(ex2f(z0), ex2f(z1));
            se2 = f2add(se2, ep);
            sa2 = f2fma(xp, ep, sa2);
        }
        {
            const u64 xp = pk2(xg.z, xg.w);
            const u64 zp = f2fma(tjp, xp, stp);
            float z0, z1;
            upk2(z0, z1, zp);
            const u64 ep = pk2(ex2f(z0), ex2f(z1));
            se2 = f2add(se2, ep);
            sa2 = f2fma(xp, ep, sa2);
        }
    }
    float lo, hi;
    upk2(lo, hi, se2); const float se = lo + hi;
    upk2(lo, hi, sa2); const float sa = lo + hi;
    const float mj = __fdividef(sa, se);  // m at this lane's node

    // ---- DCT-8 per quarter: lane (h, ni) accumulates coeff ni of quarter h
    float ci = 0.f;
    const int hbase = lane & 24;  // h*8
#pragma unroll
    for (int j = 0; j < 8; j++) {
        const float mjj = __shfl_sync(0xffffffffu, mj, hbase + j);
        ci = fmaf(At[j * 8 + ni], mjj, ci);
    }
    // coeff i of quarter q now lives in lane q*8 + i

    // ---- Clenshaw-7 at this lane's 4 query points (coeffs via dynamic shfl)
    const float tq0 = fmaf(ta, xv.x, tc);
    const float tq1 = fmaf(ta, xv.y, tc);
    const float tq2 = fmaf(ta, xv.z, tc);
    const float tq3 = fmaf(ta, xv.w, tc);
    const int q0 = min(3, max(0, __float2int_rd((tq0 - tlo) * invqw)));
    const int q1 = min(3, max(0, __float2int_rd((tq1 - tlo) * invqw)));
    const int q2 = min(3, max(0, __float2int_rd((tq2 - tlo) * invqw)));
    const int q3 = min(3, max(0, __float2int_rd((tq3 - tlo) * invqw)));
    const int b0 = q0 << 3, b1 = q1 << 3, b2 = q2 << 3, b3 = q3 << 3;
    const float c0q = fmaf((float)q0 + 0.5f, qw, tlo);
    const float c1q = fmaf((float)q1 + 0.5f, qw, tlo);
    const float c2q = fmaf((float)q2 + 0.5f, qw, tlo);
    const float c3q = fmaf((float)q3 + 0.5f, qw, tlo);
    const float s0 = fminf(1.f, fmaxf(-1.f, (tq0 - c0q) * invrq));
    const float s1 = fminf(1.f, fmaxf(-1.f, (tq1 - c1q) * invrq));
    const float s2 = fminf(1.f, fmaxf(-1.f, (tq2 - c2q) * invrq));
    const float s3 = fminf(1.f, fmaxf(-1.f, (tq3 - c3q) * invrq));
    const float d0 = 2.f * s0, d1 = 2.f * s1, d2 = 2.f * s2, d3 = 2.f * s3;

    float a1_0 = 0.f, a2_0 = 0.f;
    float a1_1 = 0.f, a2_1 = 0.f;
    float a1_2 = 0.f, a2_2 = 0.f;
    float a1_3 = 0.f, a2_3 = 0.f;
#pragma unroll
    for (int i = 7; i >= 1; i--) {
        const float cc0 = __shfl_sync(0xffffffffu, ci, b0 + i);
        const float cc1 = __shfl_sync(0xffffffffu, ci, b1 + i);
        const float cc2 = __shfl_sync(0xffffffffu, ci, b2 + i);
        const float cc3 = __shfl_sync(0xffffffffu, ci, b3 + i);
        float nb;
        nb = fmaf(d0, a1_0, cc0 - a2_0); a2_0 = a1_0; a1_0 = nb;
        nb = fmaf(d1, a1_1, cc1 - a2_1); a2_1 = a1_1; a1_1 = nb;
        nb = fmaf(d2, a1_2, cc2 - a2_2); a2_2 = a1_2; a1_2 = nb;
        nb = fmaf(d3, a1_3, cc3 - a2_3); a2_3 = a1_3; a1_3 = nb;
    }
    const float cz0 = __shfl_sync(0xffffffffu, ci, b0);
    const float cz1 = __shfl_sync(0xffffffffu, ci, b1);
    const float cz2 = __shfl_sync(0xffffffffu, ci, b2);
    const float cz3 = __shfl_sync(0xffffffffu, ci, b3);
    const float m0 = fmaf(s0, a1_0, cz0 - a2_0);
    const float m1 = fmaf(s1, a1_1, cz1 - a2_1);
    const float m2 = fmaf(s2, a1_2, cz2 - a2_2);
    const float m3 = fmaf(s3, a1_3, cz3 - a2_3);

    float msum = (m0 + m1) + (m2 + m3);
#pragma unroll
    for (int off = 16; off > 0; off >>= 1)
        msum += __shfl_xor_sync(0xffffffffu, msum, off);

    if (lane == 0)
        out[b] = fmaf(alpha, msum, beta);
}

extern "C" void kernel_launch(void* const* d_in, const int* in_sizes, int n_in,
                              void* d_out, int out_size) {
    const float* x  = (const float*)d_in[0];
    const float* Wt = (const float*)d_in[1];
    const float* bt = (const float*)d_in[2];
    const float* Wq = (const float*)d_in[3];
    const float* bq = (const float*)d_in[4];
    const float* Wk = (const float*)d_in[5];
    const float* bk = (const float*)d_in[6];
    const float* Wv = (const float*)d_in[7];
    const float* bv = (const float*)d_in[8];
    const float* Wo = (const float*)d_in[9];
    const float* bo = (const float*)d_in[10];
    float* out = (float*)d_out;

    const int B = in_sizes[0] / 128;

    precompute_kernel<<<1, 192>>>(Wt, bt, Wq, bq, Wk, bk, Wv, bv, Wo, bo);

    // PDL: main kernel launches while precompute runs; it synchronizes on the
    // precompute grid only right before reading g_c.
    cudaLaunchConfig_t cfg = {};
    cfg.gridDim = dim3((unsigned)((B + 7) / 8));
    cfg.blockDim = dim3(256);
    cudaLaunchAttribute attr[1];
    attr[0].id = cudaLaunchAttributeProgrammaticStreamSerialization;
    attr[0].val.programmaticStreamSerializationAllowed = 1;
    cfg.attrs = attr;
    cfg.numAttrs = 1;
    cudaLaunchKernelEx(&cfg, attn_cheb4_kernel, x, out, B);
}